// round 17
// baseline (speedup 1.0000x reference)
#include <cuda_runtime.h>
#include <cuda_bf16.h>

// ---------------- problem constants ----------------
#define BB    32
#define NNc   6
#define BN    192
#define INCH  768
#define FHc   4
#define FWc   6
#define PXc   24
#define OCH   105
#define DDc   41
#define CCc   64
#define KSP   4
#define KC    192
#define NXc   200
#define NYc   200
#define GRID_PER_B (CCc*NXc*NYc)            // 2,560,000
#define FINAL_ELEMS ((size_t)BB*GRID_PER_B) // 81,920,000
#define NPTS  (BN*DDc*PXc)                  // 188,928

// tiling for BEV accumulation: 2 ix-rows per tile
#define TROWS 2
#define TILES_PER_B (NXc/TROWS)             // 100
#define NTILES (BB*TILES_PER_B)             // 3200
#define BINCAP 6144
#define CPAD 65                             // [cell*CPAD + c]
#define TILE_FLOATS (TROWS*NYc*CPAD)        // 26000 floats = 104 KB

// f32x2 packed math (sm_103a FFMA2, PTX-only)
#define FMA_F32X2(d,a,b,c) \
    asm("fma.rn.f32x2 %0, %1, %2, %3;" : "=l"(d) : "l"(a), "l"(b), "l"(c))
#define PACKF2(d, lo, hi) \
    asm("mov.b64 %0, {%1, %2};" : "=l"(d) : "r"(__float_as_uint(lo)), "r"(__float_as_uint(hi)))

// ---------------- scratch ----------------
__device__ float g_part [KSP*BN*PXc*OCH];
__device__ float g_depth[BN*PXc*DDc];
__device__ float g_feat [BN*PXc*CCc];
__device__ int   g_bincnt[NTILES];
__device__ unsigned int g_bins[(size_t)NTILES*BINCAP];

// ---------------- kernel 1: 1x1 conv, K-split, FFMA2 pixel-pairing ----------------
// grid = (BN/2)*KSP = 384 per half; bn0 = 0 or 96
__global__ __launch_bounds__(162) void k_conv(const float* __restrict__ x,
                                              const float* __restrict__ wmat,
                                              int bn0) {
    const int bn = bn0 + (blockIdx.x >> 2);
    const int ks = blockIdx.x & 3;
    __shared__ float xs[KC*PXc];     // 18.0 KB
    __shared__ float ws[108*69];     // 29.1 KB
    const int tid = threadIdx.x;
    const int pxg = tid % 6;
    const int og  = tid / 6;

    const float4* xg = (const float4*)(x + (size_t)bn*INCH*PXc + (size_t)ks*KC*PXc);
    for (int i = tid; i < KC*PXc/4; i += 162) ((float4*)xs)[i] = xg[i];

    unsigned long long a01[4], a23[4];
    #pragma unroll
    for (int j = 0; j < 4; ++j) { a01[j] = 0ULL; a23[j] = 0ULL; }

    for (int sub = 0; sub < 3; ++sub) {
        __syncthreads();
        for (int i = tid; i < 108*16; i += 162) {
            int o  = i >> 4;
            int c4 = i & 15;
            float4 v = make_float4(0.f,0.f,0.f,0.f);
            if (o < OCH)
                v = *(const float4*)(wmat + (size_t)o*INCH + ks*KC + sub*64 + c4*4);
            int base = o*69 + c4*4;
            ws[base+0]=v.x; ws[base+1]=v.y; ws[base+2]=v.z; ws[base+3]=v.w;
        }
        __syncthreads();
        #pragma unroll 4
        for (int c = 0; c < 64; ++c) {
            float4 xv = *(const float4*)&xs[(sub*64 + c)*PXc + pxg*4];
            unsigned long long x01, x23;
            PACKF2(x01, xv.x, xv.y);
            PACKF2(x23, xv.z, xv.w);
            #pragma unroll
            for (int j = 0; j < 4; ++j) {
                float wv = ws[(og*4 + j)*69 + c];
                unsigned long long wp;
                PACKF2(wp, wv, wv);
                FMA_F32X2(a01[j], wp, x01, a01[j]);
                FMA_F32X2(a23[j], wp, x23, a23[j]);
            }
        }
    }

    #pragma unroll
    for (int j = 0; j < 4; ++j) {
        int o = og*4 + j;
        if (o >= OCH) continue;
        float v0 = __uint_as_float((unsigned)(a01[j] & 0xffffffffu));
        float v1 = __uint_as_float((unsigned)(a01[j] >> 32));
        float v2 = __uint_as_float((unsigned)(a23[j] & 0xffffffffu));
        float v3 = __uint_as_float((unsigned)(a23[j] >> 32));
        size_t base = (((size_t)ks*BN + bn)*PXc + pxg*4)*OCH + o;
        g_part[base]         = v0;
        g_part[base +   OCH] = v1;
        g_part[base + 2*OCH] = v2;
        g_part[base + 3*OCH] = v3;
    }
}

// ---------------- kernel 2: reduce + bias + softmax + split ----------------
// grid = 576 per half; pid0 = 0 or 2304
__global__ __launch_bounds__(128) void k_softmax(const float* __restrict__ bias,
                                                 float* __restrict__ out_logit,
                                                 int pid0) {
    const int warp = threadIdx.x >> 5;
    const int lane = threadIdx.x & 31;
    const int pid  = pid0 + blockIdx.x*4 + warp;
    const int bn   = pid / PXc;
    const int px   = pid % PXc;

    float y[4];
    #pragma unroll
    for (int k = 0; k < 4; ++k) {
        int id = lane + 32*k;
        float v = 0.0f;
        if (id < OCH) {
            v = bias[id];
            #pragma unroll
            for (int ks = 0; ks < KSP; ++ks)
                v += g_part[(((size_t)ks*BN + bn)*PXc + px)*OCH + id];
        }
        y[k] = v;
    }

    float m = y[0];
    if (lane < 9) m = fmaxf(m, y[1]);
    #pragma unroll
    for (int s = 16; s; s >>= 1) m = fmaxf(m, __shfl_xor_sync(0xffffffffu, m, s));
    float e0 = expf(y[0] - m);
    float e1 = (lane < 9) ? expf(y[1] - m) : 0.0f;
    float ssum = e0 + e1;
    #pragma unroll
    for (int s = 16; s; s >>= 1) ssum += __shfl_xor_sync(0xffffffffu, ssum, s);

    out_logit[((size_t)bn*DDc + lane)*PXc + px] = y[0];
    if (lane < 9) out_logit[((size_t)bn*DDc + lane + 32)*PXc + px] = y[1];

    size_t pbase = (size_t)(bn*PXc + px);
    g_depth[pbase*DDc + lane] = e0 / ssum;
    if (lane < 9) g_depth[pbase*DDc + lane + 32] = e1 / ssum;

    if (lane >= 9) g_feat[pbase*CCc + (lane + 32 - 41)] = y[1];
    g_feat[pbase*CCc + (lane + 64 - 41)] = y[2];
    if (lane < 9) g_feat[pbase*CCc + (lane + 96 - 41)] = y[3];
}

// ---------------- kernel 3: geometry + warp-aggregated binning ----------------
// grid = 369 per half; pbase0 = 0 or NPTS/2 (94464)
__global__ __launch_bounds__(256) void k_bin(const float* __restrict__ rots,
                                             const float* __restrict__ intr,
                                             const float* __restrict__ trans,
                                             int pbase0) {
    const int p = pbase0 + blockIdx.x*256 + threadIdx.x;

    const int bn = p / (DDc*PXc);
    const int r  = p % (DDc*PXc);
    const int d  = r / PXc;
    const int px = r % PXc;
    const int h  = px / FWc;
    const int w  = px % FWc;

    const float dsv = 4.0f + (float)d;
    const float p0 = (float)((double)w * (199.0/5.0)) * dsv;
    const float p1 = (float)((double)h * (149.0/3.0)) * dsv;
    const float p2 = dsv;

    const float* K = intr + bn*9;
    float a=K[0],b=K[1],c=K[2],dd=K[3],e=K[4],f=K[5],g=K[6],hh=K[7],i=K[8];
    float A  =  (e*i - f*hh);
    float Bc = -(dd*i - f*g);
    float Cc =  (dd*hh - e*g);
    float idet = 1.0f/(a*A + b*Bc + c*Cc);
    float q0 = (A*p0  - (b*i-c*hh)*p1 + (b*f-c*e)*p2)  * idet;
    float q1 = (Bc*p0 + (a*i-c*g)*p1  - (a*f-c*dd)*p2) * idet;
    float q2 = (Cc*p0 - (a*hh-b*g)*p1 + (a*e-b*dd)*p2) * idet;
    const float* R = rots  + bn*9;
    const float* T = trans + bn*3;
    float gx = R[0]*q0 + R[1]*q1 + R[2]*q2 + T[0];
    float gy = R[3]*q0 + R[4]*q1 + R[5]*q2 + T[1];
    float gz = R[6]*q0 + R[7]*q1 + R[8]*q2 + T[2];

    // truncation toward zero == .astype(int32)
    int ix = (int)((gx + 50.0f) / 0.5f);
    int iy = (int)((gy + 50.0f) / 0.5f);
    int iz = (int)((gz + 10.0f) / 20.0f);
    bool kept = (ix >= 0 && ix < NXc && iy >= 0 && iy < NYc && iz == 0);

    if (kept) {
        const int bidx = bn / NNc;
        const int tile = bidx*TILES_PER_B + (ix >> 1);
        const int cell = (ix & 1)*NYc + iy;
        const int pb   = bn*PXc + px;

        unsigned peers  = __match_any_sync(__activemask(), tile);
        int      leader = __ffs(peers) - 1;
        int      lane   = threadIdx.x & 31;
        int      rank   = __popc(peers & ((1u << lane) - 1u));
        int base;
        if (lane == leader) base = atomicAdd(&g_bincnt[tile], __popc(peers));
        base = __shfl_sync(peers, base, leader);
        g_bins[(size_t)tile*BINCAP + base + rank] =
            ((unsigned)pb << 15) | ((unsigned)d << 9) | (unsigned)cell;
    }
}

// ---------------- kernel 4: per-tile SMEM accumulate + full write-out ----------------
// grid = 1600 per half; tile0 = 0 or 1600
__global__ __launch_bounds__(1024) void k_tile(float* __restrict__ out, int tile0) {
    extern __shared__ float s[];
    const int tile = tile0 + blockIdx.x;
    const int b    = tile / TILES_PER_B;
    const int tix  = tile % TILES_PER_B;
    const int tid  = threadIdx.x;
    const int lane = tid & 31;
    const int wid  = tid >> 5;

    const int cnt = g_bincnt[tile];

    // empty tile: pure float4 zero store
    if (cnt == 0) {
        const float4 z = make_float4(0.f,0.f,0.f,0.f);
        #pragma unroll
        for (int pp = 0; pp < 4; ++pp) {
            int pr  = wid*4 + pp;
            int c   = pr >> 1;
            int row = pr & 1;
            float4* op = (float4*)(out + (size_t)b*GRID_PER_B
                                   + ((size_t)c*NXc + tix*TROWS + row)*NYc) + lane;
            op[0] = z;
            if (lane < 18) op[32] = z;
        }
        return;
    }

    for (int i = tid; i < TILE_FLOATS/4; i += 1024)
        ((float4*)s)[i] = make_float4(0.f,0.f,0.f,0.f);
    __syncthreads();

    const unsigned* rec = g_bins + (size_t)tile*BINCAP;
    for (int i = wid; i < cnt; i += 32) {
        unsigned e = rec[i];
        int cell = (int)(e & 511u);
        int d    = (int)((e >> 9) & 63u);
        int pb   = (int)(e >> 15);
        float dep = g_depth[pb*DDc + d];
        const float* fp = g_feat + (size_t)pb*CCc;
        float f0 = fp[lane];
        float f1 = fp[lane + 32];
        atomicAdd(&s[cell*CPAD + lane],      dep*f0);
        atomicAdd(&s[cell*CPAD + lane + 32], dep*f1);
    }
    __syncthreads();

    #pragma unroll
    for (int pp = 0; pp < 4; ++pp) {
        int pr  = wid*4 + pp;
        int c   = pr >> 1;
        int row = pr & 1;
        const float* sp = s + (row*NYc + lane)*CPAD + c;
        float* op = out + (size_t)b*GRID_PER_B
                        + ((size_t)c*NXc + tix*TROWS + row)*NYc + lane;
        #pragma unroll
        for (int kk = 0; kk < 6; ++kk)
            op[kk*32] = sp[kk*32*CPAD];
        if (lane < 8)
            op[6*32] = sp[6*32*CPAD];
    }
}

// ---------------- launch: batch-halved software pipeline ----------------
extern "C" void kernel_launch(void* const* d_in, const int* in_sizes, int n_in,
                              void* d_out, int out_size) {
    const float* x     = (const float*)d_in[0];
    const float* rots  = (const float*)d_in[1];
    const float* trans = (const float*)d_in[2];
    const float* intr  = (const float*)d_in[3];
    const float* cw    = (const float*)d_in[4];
    const float* cb    = (const float*)d_in[5];
    float* out = (float*)d_out;

    static void* bincnt_ptr = nullptr;
    static cudaStream_t s2 = nullptr;
    static cudaEvent_t evH0 = nullptr, evT0 = nullptr;
    if (!bincnt_ptr) {
        cudaFuncSetAttribute(k_tile, cudaFuncAttributeMaxDynamicSharedMemorySize,
                             TILE_FLOATS*sizeof(float));
        cudaGetSymbolAddress(&bincnt_ptr, g_bincnt);
        cudaStreamCreateWithFlags(&s2, cudaStreamNonBlocking);
        cudaEventCreateWithFlags(&evH0, cudaEventDisableTiming);
        cudaEventCreateWithFlags(&evT0, cudaEventDisableTiming);
    }

    cudaMemsetAsync(bincnt_ptr, 0, NTILES*sizeof(int), 0);

    // ---- half 0 compute (b 0..15 / bn 0..95) on main stream ----
    k_conv   <<<(BN/2)*KSP, 162>>>(x, cw, 0);
    k_softmax<<<(BN*PXc)/8, 128>>>(cb, out + FINAL_ELEMS, 0);
    k_bin    <<<NPTS/2/256, 256>>>(rots, intr, trans, 0);
    cudaEventRecord(evH0, 0);

    // ---- k_tile half 0 on side stream (DRAM-bound), overlapping half-1 compute ----
    cudaStreamWaitEvent(s2, evH0, 0);
    k_tile<<<NTILES/2, 1024, TILE_FLOATS*sizeof(float), s2>>>(out, 0);
    cudaEventRecord(evT0, s2);

    // ---- half 1 compute (b 16..31 / bn 96..191) on main stream ----
    k_conv   <<<(BN/2)*KSP, 162>>>(x, cw, BN/2);
    k_softmax<<<(BN*PXc)/8, 128>>>(cb, out + FINAL_ELEMS, (BN*PXc)/2);
    k_bin    <<<NPTS/2/256, 256>>>(rots, intr, trans, NPTS/2);

    // ---- k_tile half 1 on main stream, then join side stream ----
    k_tile<<<NTILES/2, 1024, TILE_FLOATS*sizeof(float)>>>(out, NTILES/2);
    cudaStreamWaitEvent(0, evT0, 0);
}